// round 3
// baseline (speedup 1.0000x reference)
#include <cuda_runtime.h>
#include <cuda_bf16.h>
#include <cstdint>

#define DD 128
#define SMAX 4096
#define NMAX 1048576

// ---------------- scratch (device globals; no allocs allowed) ----------------
__device__ float          g_xs[SMAX * DD];          // segment sums (fp32)
__device__ float          g_xm[SMAX * DD];          // xs @ Lambda^T (fp32)
__device__ __nv_bfloat16  g_xbf[(size_t)NMAX * DD]; // bf16 copy of x (256 MB)
__device__ __nv_bfloat16  g_Gb[DD * DD];            // bf16 Gamma_W

__device__ __forceinline__ uint32_t smem_u32(const void* p) {
    uint32_t a;
    asm("{ .reg .u64 t; cvta.to.shared.u64 t, %1; cvt.u32.u64 %0, t; }"
        : "=r"(a) : "l"(p));
    return a;
}

// ---------------- kernel 0: zero xs + convert Gamma_W -> bf16 ----------------
__global__ void prep_kernel(const float* __restrict__ GW) {
    int i = blockIdx.x * blockDim.x + threadIdx.x;
    if (i < SMAX * DD) g_xs[i] = 0.0f;
    if (i < DD * DD)   g_Gb[i] = __float2bfloat16(GW[i]);
}

// ---------------- kernel 1: segment sum + bf16 convert of x ----------------
#define SEG_ROWS 512
__global__ __launch_bounds__(128) void segsum_kernel(
    const float* __restrict__ x, const int* __restrict__ seg, int n)
{
    int t = threadIdx.x;                 // column 0..127
    int base = blockIdx.x * SEG_ROWS;
    float acc = 0.0f;
    int cur = -1;
    #pragma unroll 4
    for (int r = 0; r < SEG_ROWS; r++) {
        int row = base + r;
        if (row >= n) break;
        int s = seg[row];                // warp-uniform broadcast load
        if (s != cur) {
            if (cur >= 0) atomicAdd(&g_xs[(size_t)cur * DD + t], acc);
            acc = 0.0f;
            cur = s;
        }
        float v = x[(size_t)row * DD + t];
        acc += v;
        g_xbf[(size_t)row * DD + t] = __float2bfloat16(v);
    }
    if (cur >= 0) atomicAdd(&g_xs[(size_t)cur * DD + t], acc);
}

// ---------------- kernel 2: xm = xs @ Lambda^T (fp32, 32 segs/block) --------
__global__ __launch_bounds__(128) void xm_kernel(const float* __restrict__ LW) {
    __shared__ float xsh[32 * DD];
    int t = threadIdx.x;
    int s0 = blockIdx.x * 32;
    #pragma unroll
    for (int j = 0; j < 32; j++)
        xsh[j * DD + t] = g_xs[(size_t)(s0 + j) * DD + t];
    __syncthreads();
    float acc[32];
    #pragma unroll
    for (int j = 0; j < 32; j++) acc[j] = 0.0f;
    const float* lrow = LW + (size_t)t * DD;   // xm[s][t] = sum_k xs[s][k]*LW[t][k]
    #pragma unroll 4
    for (int k = 0; k < DD; k++) {
        float lw = lrow[k];
        #pragma unroll
        for (int j = 0; j < 32; j++) acc[j] += xsh[j * DD + k] * lw;
    }
    #pragma unroll
    for (int j = 0; j < 32; j++)
        g_xm[(size_t)(s0 + j) * DD + t] = acc[j];
}

// ---------------- kernel 3: out = x @ Gamma^T + b - xm[seg]  (HMMA) ---------
// mma.sync m16n8k16 bf16/f32. CTA tile 128x128xK128; 8 warps in 4(M) x 2(N);
// each warp: 32(M) x 64(N) = 2 x 8 mma tiles. A,B staged in smem with padded
// stride 136 bf16 (272 B -> 4-bank shift/row, ldmatrix conflict-free).
#define ASTRIDE 136
#define AB_ELEMS (DD * ASTRIDE)
#define GEMM_SMEM (2 * AB_ELEMS * 2)    /* 69632 B */

__global__ __launch_bounds__(256) void gemm_kernel(
    const int* __restrict__ seg, const float* __restrict__ bias,
    float* __restrict__ out, int n)
{
    extern __shared__ __nv_bfloat16 sm[];
    __nv_bfloat16* As = sm;
    __nv_bfloat16* Bs = sm + AB_ELEMS;

    int tid  = threadIdx.x;
    int lane = tid & 31;
    int wid  = tid >> 5;
    int m0   = blockIdx.x * 128;
    bool full = (m0 + 127 < n);

    // ---- stage A (x rows, bf16) and B (Gamma) in smem ----
    #pragma unroll
    for (int i = 0; i < 8; i++) {
        int idx = tid + i * 256;          // 0..2047
        int row = idx >> 4, u = idx & 15; // u*8 = col
        uint4 v = make_uint4(0, 0, 0, 0);
        if (full || m0 + row < n)
            v = *(const uint4*)(g_xbf + (size_t)(m0 + row) * DD + u * 8);
        *(uint4*)(As + row * ASTRIDE + u * 8) = v;
        uint4 b = *(const uint4*)(g_Gb + row * DD + u * 8);
        *(uint4*)(Bs + row * ASTRIDE + u * 8) = b;
    }
    __syncthreads();

    int wm = (wid & 3) * 32;   // warp M offset
    int wn = (wid >> 2) * 64;  // warp N offset

    float acc[2][8][4];
    #pragma unroll
    for (int a = 0; a < 2; a++)
        #pragma unroll
        for (int b = 0; b < 8; b++)
            #pragma unroll
            for (int c = 0; c < 4; c++) acc[a][b][c] = 0.0f;

    // per-lane ldmatrix row selectors
    int g  = lane >> 3, lr = lane & 7;
    int a_m = (g & 1) * 8 + lr;   // groups 0/2 -> rows 0-7, 1/3 -> 8-15
    int a_k = (g >> 1) * 8;       // groups 0,1 -> k0, 2,3 -> k8
    int b_n = (g >> 1) * 8 + lr;  // groups 0,1 -> n0-7, 2,3 -> n8-15
    int b_k = (g & 1) * 8;        // groups 0,2 -> k0, 1,3 -> k8

    uint32_t a_base0 = smem_u32(As) + (uint32_t)(((wm + a_m) * ASTRIDE + a_k) * 2);
    uint32_t b_base0 = smem_u32(Bs) + (uint32_t)(((wn + b_n) * ASTRIDE + b_k) * 2);

    #pragma unroll
    for (int kk = 0; kk < 8; kk++) {
        uint32_t koff = kk * 16 * 2;
        uint32_t afrag[2][4];
        #pragma unroll
        for (int tm = 0; tm < 2; tm++) {
            uint32_t addr = a_base0 + tm * (16 * ASTRIDE * 2) + koff;
            asm volatile("ldmatrix.sync.aligned.m8n8.x4.shared.b16 "
                         "{%0,%1,%2,%3}, [%4];"
                         : "=r"(afrag[tm][0]), "=r"(afrag[tm][1]),
                           "=r"(afrag[tm][2]), "=r"(afrag[tm][3])
                         : "r"(addr));
        }
        uint32_t bfrag[4][4];   // [pair p][regs: nt(2p) k0,k8 ; nt(2p+1) k0,k8]
        #pragma unroll
        for (int p = 0; p < 4; p++) {
            uint32_t addr = b_base0 + p * (16 * ASTRIDE * 2) + koff;
            asm volatile("ldmatrix.sync.aligned.m8n8.x4.shared.b16 "
                         "{%0,%1,%2,%3}, [%4];"
                         : "=r"(bfrag[p][0]), "=r"(bfrag[p][1]),
                           "=r"(bfrag[p][2]), "=r"(bfrag[p][3])
                         : "r"(addr));
        }
        #pragma unroll
        for (int tm = 0; tm < 2; tm++) {
            #pragma unroll
            for (int tn = 0; tn < 8; tn++) {
                uint32_t br0 = bfrag[tn >> 1][(tn & 1) * 2];
                uint32_t br1 = bfrag[tn >> 1][(tn & 1) * 2 + 1];
                asm volatile(
                    "mma.sync.aligned.m16n8k16.row.col.f32.bf16.bf16.f32 "
                    "{%0,%1,%2,%3}, {%4,%5,%6,%7}, {%8,%9}, {%0,%1,%2,%3};"
                    : "+f"(acc[tm][tn][0]), "+f"(acc[tm][tn][1]),
                      "+f"(acc[tm][tn][2]), "+f"(acc[tm][tn][3])
                    : "r"(afrag[tm][0]), "r"(afrag[tm][1]),
                      "r"(afrag[tm][2]), "r"(afrag[tm][3]),
                      "r"(br0), "r"(br1));
            }
        }
    }

    // ---- epilogue: + bias - xm[seg[m]], float2 stores (full 32B sectors) ----
    int qr = lane >> 2, qc = 2 * (lane & 3);
    float2 bv[8];
    #pragma unroll
    for (int tn = 0; tn < 8; tn++)
        bv[tn] = *(const float2*)(bias + wn + tn * 8 + qc);

    #pragma unroll
    for (int tm = 0; tm < 2; tm++) {
        #pragma unroll
        for (int half = 0; half < 2; half++) {
            int mrow = wm + tm * 16 + qr + half * 8;
            int m = m0 + mrow;
            if (!full && m >= n) continue;
            int sid = seg[m];
            const float* xmr = g_xm + (size_t)sid * DD;
            float* orow = out + (size_t)m * DD;
            #pragma unroll
            for (int tn = 0; tn < 8; tn++) {
                int nc = wn + tn * 8 + qc;
                float2 xv = *(const float2*)(xmr + nc);
                float2 r;
                r.x = acc[tm][tn][half * 2 + 0] + bv[tn].x - xv.x;
                r.y = acc[tm][tn][half * 2 + 1] + bv[tn].y - xv.y;
                *(float2*)(orow + nc) = r;
            }
        }
    }
}

// ---------------- launch ----------------
extern "C" void kernel_launch(void* const* d_in, const int* in_sizes, int n_in,
                              void* d_out, int out_size)
{
    const float* x   = (const float*)d_in[0];
    const int*   seg = (const int*)d_in[1];
    // d_in[2] = num_segments (statically 4096 here)
    const float* GW  = (const float*)d_in[3];
    const float* Gb  = (const float*)d_in[4];
    const float* LW  = (const float*)d_in[5];
    float* out = (float*)d_out;
    int n = in_sizes[0] / DD;

    cudaFuncSetAttribute(gemm_kernel,
                         cudaFuncAttributeMaxDynamicSharedMemorySize, GEMM_SMEM);

    prep_kernel<<<(SMAX * DD + 255) / 256, 256>>>(GW);
    segsum_kernel<<<(n + SEG_ROWS - 1) / SEG_ROWS, 128>>>(x, seg, n);
    xm_kernel<<<SMAX / 32, 128>>>(LW);
    gemm_kernel<<<(n + 127) / 128, 256, GEMM_SMEM>>>(seg, Gb, out, n);
}

// round 4
// speedup vs baseline: 1.6381x; 1.6381x over previous
#include <cuda_runtime.h>
#include <cuda_bf16.h>
#include <cstdint>

#define DD 128
#define SMAX 4096
#define NMAX 1048576

// ---------------- scratch (device globals; no allocs allowed) ----------------
__device__ float          g_xs[SMAX * DD];          // segment sums (fp32)
__device__ float          g_xm[SMAX * DD];          // xs @ Lambda^T (fp32)
__device__ __nv_bfloat16  g_xbf[(size_t)NMAX * DD]; // bf16 copy of x (256 MB)
__device__ __nv_bfloat16  g_Gb[DD * DD];            // bf16 Gamma_W

__device__ __forceinline__ uint32_t smem_u32(const void* p) {
    uint32_t a;
    asm("{ .reg .u64 t; cvta.to.shared.u64 t, %1; cvt.u32.u64 %0, t; }"
        : "=r"(a) : "l"(p));
    return a;
}
__device__ __forceinline__ void cp_async16(uint32_t dst, const void* src) {
    asm volatile("cp.async.cg.shared.global [%0], [%1], 16;"
                 :: "r"(dst), "l"(src));
}
// 16B-unit swizzle: row-dependent XOR keeps ldmatrix 8-row reads conflict-free
#define SWZB(u, lr3) ((((((u) ^ (lr3)) & 7) | ((u) & 8))) << 4)

// ---------------- kernel 0: zero xs + convert Gamma_W -> bf16 ----------------
__global__ void prep_kernel(const float* __restrict__ GW) {
    int i = blockIdx.x * blockDim.x + threadIdx.x;
    if (i < SMAX * DD) g_xs[i] = 0.0f;
    if (i < DD * DD)   g_Gb[i] = __float2bfloat16(GW[i]);
}

// ---------------- kernel 1: segment sum + bf16 convert of x ----------------
// warp = 32 lanes x float4 = one 512B row; each warp owns SS_ROWS rows.
#define SS_ROWS 128
__global__ __launch_bounds__(256) void segsum_kernel(
    const float* __restrict__ x, const int* __restrict__ seg, int n)
{
    int lane = threadIdx.x & 31;
    int w = blockIdx.x * 8 + (threadIdx.x >> 5);
    int base = w * SS_ROWS;
    if (base >= n) return;
    int limit = n - base; if (limit > SS_ROWS) limit = SS_ROWS;

    float4 acc = make_float4(0.f, 0.f, 0.f, 0.f);
    int cur = -1;

    int r = 0;
    for (; r + 4 <= limit; r += 4) {
        int row = base + r;
        int s0 = seg[row], s1 = seg[row + 1], s2 = seg[row + 2], s3 = seg[row + 3];
        float4 v0 = *(const float4*)(x + (size_t)(row    ) * DD + lane * 4);
        float4 v1 = *(const float4*)(x + (size_t)(row + 1) * DD + lane * 4);
        float4 v2 = *(const float4*)(x + (size_t)(row + 2) * DD + lane * 4);
        float4 v3 = *(const float4*)(x + (size_t)(row + 3) * DD + lane * 4);
        #pragma unroll
        for (int j = 0; j < 4; j++) {
            float4 v = (j == 0) ? v0 : (j == 1) ? v1 : (j == 2) ? v2 : v3;
            int    s = (j == 0) ? s0 : (j == 1) ? s1 : (j == 2) ? s2 : s3;
            if (s != cur) {
                if (cur >= 0) {
                    float* p = g_xs + (size_t)cur * DD + lane * 4;
                    atomicAdd(p + 0, acc.x); atomicAdd(p + 1, acc.y);
                    atomicAdd(p + 2, acc.z); atomicAdd(p + 3, acc.w);
                }
                acc = make_float4(0.f, 0.f, 0.f, 0.f);
                cur = s;
            }
            acc.x += v.x; acc.y += v.y; acc.z += v.z; acc.w += v.w;
            __nv_bfloat162 h0 = __float22bfloat162_rn(make_float2(v.x, v.y));
            __nv_bfloat162 h1 = __float22bfloat162_rn(make_float2(v.z, v.w));
            uint2 pk = make_uint2(reinterpret_cast<uint32_t&>(h0),
                                  reinterpret_cast<uint32_t&>(h1));
            *(uint2*)(g_xbf + (size_t)(row + j) * DD + lane * 4) = pk;
        }
    }
    for (; r < limit; r++) {
        int row = base + r;
        int s = seg[row];
        float4 v = *(const float4*)(x + (size_t)row * DD + lane * 4);
        if (s != cur) {
            if (cur >= 0) {
                float* p = g_xs + (size_t)cur * DD + lane * 4;
                atomicAdd(p + 0, acc.x); atomicAdd(p + 1, acc.y);
                atomicAdd(p + 2, acc.z); atomicAdd(p + 3, acc.w);
            }
            acc = make_float4(0.f, 0.f, 0.f, 0.f);
            cur = s;
        }
        acc.x += v.x; acc.y += v.y; acc.z += v.z; acc.w += v.w;
        __nv_bfloat162 h0 = __float22bfloat162_rn(make_float2(v.x, v.y));
        __nv_bfloat162 h1 = __float22bfloat162_rn(make_float2(v.z, v.w));
        uint2 pk = make_uint2(reinterpret_cast<uint32_t&>(h0),
                              reinterpret_cast<uint32_t&>(h1));
        *(uint2*)(g_xbf + (size_t)row * DD + lane * 4) = pk;
    }
    if (cur >= 0) {
        float* p = g_xs + (size_t)cur * DD + lane * 4;
        atomicAdd(p + 0, acc.x); atomicAdd(p + 1, acc.y);
        atomicAdd(p + 2, acc.z); atomicAdd(p + 3, acc.w);
    }
}

// ---------------- kernel 2: xm = xs @ Lambda^T (fp32, 32 segs/block) --------
__global__ __launch_bounds__(128) void xm_kernel(const float* __restrict__ LW) {
    __shared__ float xsh[32 * DD];
    int t = threadIdx.x;
    int s0 = blockIdx.x * 32;
    #pragma unroll
    for (int j = 0; j < 32; j++)
        xsh[j * DD + t] = g_xs[(size_t)(s0 + j) * DD + t];
    __syncthreads();
    float acc[32];
    #pragma unroll
    for (int j = 0; j < 32; j++) acc[j] = 0.0f;
    const float* lrow = LW + (size_t)t * DD;
    #pragma unroll 4
    for (int k = 0; k < DD; k++) {
        float lw = lrow[k];
        #pragma unroll
        for (int j = 0; j < 32; j++) acc[j] += xsh[j * DD + k] * lw;
    }
    #pragma unroll
    for (int j = 0; j < 32; j++)
        g_xm[(size_t)(s0 + j) * DD + t] = acc[j];
}

// ---------------- kernel 3: persistent HMMA GEMM, cp.async double buffer ----
// smem: As[0] 32KB | As[1] 32KB | Bs 32KB  = 96 KB  (2 CTAs/SM)
#define GEMM_SMEM (3 * 32768)

__device__ __forceinline__ void stage_A(uint32_t dstbase, int t, int n, int tid) {
    int m0 = t * 128;
    #pragma unroll
    for (int i = 0; i < 8; i++) {
        int idx = tid + i * 256, row = idx >> 4, u = idx & 15;
        int gr = m0 + row; if (gr >= n) gr = n - 1;   // clamp; garbage rows never stored
        const void* src = g_xbf + (size_t)gr * DD + u * 8;
        cp_async16(dstbase + row * 256 + SWZB(u, row & 7), src);
    }
}

__global__ __launch_bounds__(256, 2) void gemm_kernel(
    const int* __restrict__ seg, const float* __restrict__ bias,
    float* __restrict__ out, int n, int ntiles)
{
    extern __shared__ char smraw[];
    uint32_t sb = smem_u32(smraw);
    uint32_t As[2] = { sb, sb + 32768 };
    uint32_t Bs = sb + 65536;

    int tid = threadIdx.x, lane = tid & 31, wid = tid >> 5;

    // stage B (Gamma) once + first A tile, one cp.async group
    #pragma unroll
    for (int i = 0; i < 8; i++) {
        int idx = tid + i * 256, row = idx >> 4, u = idx & 15;
        cp_async16(Bs + row * 256 + SWZB(u, row & 7), g_Gb + row * DD + u * 8);
    }
    stage_A(As[0], blockIdx.x, n, tid);
    asm volatile("cp.async.commit_group;");

    // lane geometry
    int wm = (wid & 3) * 32, wn = (wid >> 2) * 64;
    int g = lane >> 3, lr = lane & 7;
    int qr = lane >> 2, qc = 2 * (lane & 3);
    int a_m = (g & 1) * 8 + lr;
    int b_n = (g >> 1) * 8 + lr;
    int ua0 = g >> 1, ub0 = g & 1;

    uint32_t a_off[2], b_base[4];
    #pragma unroll
    for (int tm = 0; tm < 2; tm++) a_off[tm] = (uint32_t)((wm + a_m + tm * 16) * 256);
    #pragma unroll
    for (int p = 0; p < 4; p++) b_base[p] = Bs + (uint32_t)((wn + b_n + p * 16) * 256);

    float2 bv[8];
    #pragma unroll
    for (int tn = 0; tn < 8; tn++)
        bv[tn] = *(const float2*)(bias + wn + tn * 8 + qc);

    int buf = 0;
    for (int t = blockIdx.x; t < ntiles; t += gridDim.x, buf ^= 1) {
        asm volatile("cp.async.wait_group 0;" ::: "memory");
        __syncthreads();   // all stages visible; all threads past previous mma

        int tnext = t + gridDim.x;
        if (tnext < ntiles) {
            stage_A(As[buf ^ 1], tnext, n, tid);
            asm volatile("cp.async.commit_group;");
        }

        int m0 = t * 128;
        bool full = (m0 + 128 <= n);
        // prefetch segment ids for this tile's epilogue
        int sid[2][2];
        #pragma unroll
        for (int tm = 0; tm < 2; tm++)
            #pragma unroll
            for (int half = 0; half < 2; half++) {
                int m = m0 + wm + tm * 16 + qr + half * 8;
                sid[tm][half] = (full || m < n) ? seg[m] : 0;
            }

        float acc[2][8][4];
        #pragma unroll
        for (int a = 0; a < 2; a++)
            #pragma unroll
            for (int b = 0; b < 8; b++)
                #pragma unroll
                for (int c = 0; c < 4; c++) acc[a][b][c] = 0.0f;

        uint32_t ab = As[buf];
        #pragma unroll
        for (int kk = 0; kk < 8; kk++) {
            int ua = ua0 + 2 * kk, ub = ub0 + 2 * kk;
            uint32_t asw = (uint32_t)SWZB(ua, lr);
            uint32_t bsw = (uint32_t)SWZB(ub, lr);
            uint32_t afrag[2][4];
            #pragma unroll
            for (int tm = 0; tm < 2; tm++) {
                asm volatile("ldmatrix.sync.aligned.m8n8.x4.shared.b16 "
                             "{%0,%1,%2,%3}, [%4];"
                             : "=r"(afrag[tm][0]), "=r"(afrag[tm][1]),
                               "=r"(afrag[tm][2]), "=r"(afrag[tm][3])
                             : "r"(ab + a_off[tm] + asw));
            }
            uint32_t bfrag[4][4];
            #pragma unroll
            for (int p = 0; p < 4; p++) {
                asm volatile("ldmatrix.sync.aligned.m8n8.x4.shared.b16 "
                             "{%0,%1,%2,%3}, [%4];"
                             : "=r"(bfrag[p][0]), "=r"(bfrag[p][1]),
                               "=r"(bfrag[p][2]), "=r"(bfrag[p][3])
                             : "r"(b_base[p] + bsw));
            }
            #pragma unroll
            for (int tm = 0; tm < 2; tm++) {
                #pragma unroll
                for (int tn = 0; tn < 8; tn++) {
                    uint32_t br0 = bfrag[tn >> 1][(tn & 1) * 2];
                    uint32_t br1 = bfrag[tn >> 1][(tn & 1) * 2 + 1];
                    asm volatile(
                        "mma.sync.aligned.m16n8k16.row.col.f32.bf16.bf16.f32 "
                        "{%0,%1,%2,%3}, {%4,%5,%6,%7}, {%8,%9}, {%0,%1,%2,%3};"
                        : "+f"(acc[tm][tn][0]), "+f"(acc[tm][tn][1]),
                          "+f"(acc[tm][tn][2]), "+f"(acc[tm][tn][3])
                        : "r"(afrag[tm][0]), "r"(afrag[tm][1]),
                          "r"(afrag[tm][2]), "r"(afrag[tm][3]),
                          "r"(br0), "r"(br1));
                }
            }
        }

        // epilogue: + bias - xm[seg[m]], float2 stores (full sectors)
        #pragma unroll
        for (int tm = 0; tm < 2; tm++) {
            #pragma unroll
            for (int half = 0; half < 2; half++) {
                int m = m0 + wm + tm * 16 + qr + half * 8;
                if (!full && m >= n) continue;
                const float* xmr = g_xm + (size_t)sid[tm][half] * DD;
                float* orow = out + (size_t)m * DD;
                #pragma unroll
                for (int tn = 0; tn < 8; tn++) {
                    int nc = wn + tn * 8 + qc;
                    float2 xv = *(const float2*)(xmr + nc);
                    float2 rr;
                    rr.x = acc[tm][tn][half * 2 + 0] + bv[tn].x - xv.x;
                    rr.y = acc[tm][tn][half * 2 + 1] + bv[tn].y - xv.y;
                    *(float2*)(orow + nc) = rr;
                }
            }
        }
    }
}

// ---------------- launch ----------------
extern "C" void kernel_launch(void* const* d_in, const int* in_sizes, int n_in,
                              void* d_out, int out_size)
{
    const float* x   = (const float*)d_in[0];
    const int*   seg = (const int*)d_in[1];
    // d_in[2] = num_segments (statically 4096 here)
    const float* GW  = (const float*)d_in[3];
    const float* Gb  = (const float*)d_in[4];
    const float* LW  = (const float*)d_in[5];
    float* out = (float*)d_out;
    int n = in_sizes[0] / DD;
    int ntiles = (n + 127) / 128;

    cudaFuncSetAttribute(gemm_kernel,
                         cudaFuncAttributeMaxDynamicSharedMemorySize, GEMM_SMEM);

    prep_kernel<<<(SMAX * DD + 255) / 256, 256>>>(GW);
    int nwarps = (n + SS_ROWS - 1) / SS_ROWS;
    segsum_kernel<<<(nwarps + 7) / 8, 256>>>(x, seg, n);
    xm_kernel<<<SMAX / 32, 128>>>(LW);
    int grid = 296; if (grid > ntiles) grid = ntiles;
    gemm_kernel<<<grid, 256, GEMM_SMEM>>>(seg, Gb, out, n, ntiles);
}